// round 11
// baseline (speedup 1.0000x reference)
#include <cuda_runtime.h>
#include <cuda_bf16.h>
#include <cstdint>

#define NPTS 10000
#define KNB 32
#define KSZ 6
#define MCELLS 216           // 6*6*6
#define KD2 (MCELLS * 64)    // 13824
#define LDA1 896             // layer1 Kd=864 padded to 28*32
#define RPAD 10112           // 79 tiles * 128 rows
#define MT 79                // M tiles

// ---------------- device scratch (static: no allocs allowed) ----------------
__device__ float4 g_pairs[NPTS * KNB];
__device__ float  g_cnt[NPTS];
__device__ __nv_bfloat16 g_Ah[(size_t)RPAD * KD2];    // scatter output hi (280 MB)
__device__ __nv_bfloat16 g_Al[(size_t)RPAD * KD2];    // scatter output lo
__device__ __nv_bfloat16 g_Wth[64 * KD2];             // transposed W hi [Cout][lda]
__device__ __nv_bfloat16 g_Wtl[64 * KD2];             // transposed W lo
__device__ float  g_acc[NPTS * 64];                   // fp32 accumulator
__device__ float  g_X1[NPTS * 64];
__device__ float  g_X2[NPTS * 64];
__device__ float  g_X3[NPTS * 32];
__device__ int    g_mask_is_u8;

__device__ __forceinline__ float sgnf(float v) { return (v > 0.f) ? 1.f : ((v < 0.f) ? -1.f : 0.f); }

// ---------------- PTX helpers (all sm_80+ baseline; no 103a features) ----------------
__device__ __forceinline__ uint32_t smem_u32(const void* p) {
    uint32_t a;
    asm("{ .reg .u64 t; cvta.to.shared.u64 t, %1; cvt.u32.u64 %0, t; }" : "=r"(a) : "l"(p));
    return a;
}
__device__ __forceinline__ void cpa16(uint32_t dst, const void* src) {
    asm volatile("cp.async.cg.shared.global [%0], [%1], 16;" :: "r"(dst), "l"(src) : "memory");
}
__device__ __forceinline__ void ldmx4(uint32_t* r, uint32_t addr) {
    asm volatile("ldmatrix.sync.aligned.m8n8.x4.shared.b16 {%0,%1,%2,%3}, [%4];"
                 : "=r"(r[0]), "=r"(r[1]), "=r"(r[2]), "=r"(r[3]) : "r"(addr));
}
__device__ __forceinline__ void mma16816(float* d, const uint32_t* a, uint32_t b0, uint32_t b1) {
    asm volatile(
        "mma.sync.aligned.m16n8k16.row.col.f32.bf16.bf16.f32 "
        "{%0,%1,%2,%3}, {%4,%5,%6,%7}, {%8,%9}, {%0,%1,%2,%3};"
        : "+f"(d[0]), "+f"(d[1]), "+f"(d[2]), "+f"(d[3])
        : "r"(a[0]), "r"(a[1]), "r"(a[2]), "r"(a[3]), "r"(b0), "r"(b1));
}
__device__ __forceinline__ uint32_t packbf2(float v0, float v1) {
    uint32_t r;
    asm("cvt.rn.bf16x2.f32 %0, %1, %2;" : "=r"(r) : "f"(v1), "f"(v0));
    return r;
}

// ---------------- mask dtype detection ----------------
__global__ void detect_mask_kernel(const unsigned char* __restrict__ bytes) {
    int i = blockIdx.x * 256 + threadIdx.x;
    if (i >= NPTS * KNB) return;
    if ((i & 3) != 0 && bytes[i] != 0) atomicOr(&g_mask_is_u8, 1);
}
__device__ __forceinline__ unsigned read_mask(const void* m, int idx) {
    if (g_mask_is_u8) return ((const unsigned char*)m)[idx] ? 1u : 0u;
    return ((const int*)m)[idx] ? 1u : 0u;
}

// ---------------- geometry (+ fused wsplit of W1) ----------------
__global__ void geom_kernel(const float* __restrict__ pos, const int* __restrict__ nidx,
                            const void* __restrict__ nmask, const float* __restrict__ W1) {
    int idx = blockIdx.x * blockDim.x + threadIdx.x;

    // fused: transpose+split W1 into g_Wth/g_Wtl (64 x LDA1)
    if (idx < 64 * LDA1) {
        int o = idx / LDA1, k = idx - o * LDA1;
        float v = (k < MCELLS * 4) ? W1[(size_t)k * 64 + o] : 0.f;
        __nv_bfloat16 h = __float2bfloat16(v);
        __nv_bfloat16 l = __float2bfloat16(v - __bfloat162float(h));
        g_Wth[(size_t)o * LDA1 + k] = h;
        g_Wtl[(size_t)o * LDA1 + k] = l;
    }

    if (idx >= NPTS * KNB) return;
    int j = idx >> 5;
    int n = nidx[idx];
    unsigned m = read_mask(nmask, idx);

    const float EPS = 1e-12f;
    float x = (pos[n * 3 + 0] - pos[j * 3 + 0]) * (2.0f / 3.0f);
    float y = (pos[n * 3 + 1] - pos[j * 3 + 1]) * (2.0f / 3.0f);
    float z = (pos[n * 3 + 2] - pos[j * 3 + 2]) * (2.0f / 3.0f);

    float sq = x * x + y * y + z * z;
    float norm = sqrtf(fmaxf(sq, EPS));
    float rho2 = x * x + y * y;
    bool in_cone = (1.25f * z * z > rho2);
    float s, zc;
    if (in_cone) { s = sqrtf(3.0f * norm / (norm + fabsf(z))); zc = sgnf(z) * norm; }
    else         { s = norm / sqrtf(fmaxf(rho2, EPS));         zc = 1.5f * z; }
    float xc = x * s, yc = y * s;
    if (sq < EPS) { xc = 0.f; yc = 0.f; zc = 0.f; }

    float sq_xy = xc * xc + yc * yc;
    float norm_xy = sqrtf(fmaxf(sq_xy, EPS));
    bool x_major = fabsf(yc) <= fabsf(xc);
    float xd = (fabsf(xc) < EPS) ? 1.f : xc;
    float yd = (fabsf(yc) < EPS) ? 1.f : yc;
    float tx = sgnf(xc) * norm_xy, ty = sgnf(yc) * norm_xy;
    const float FOPI = 1.2732395447351628f;
    float xq, yq;
    if (x_major) { xq = tx;                        yq = tx * FOPI * atanf(yc / xd); }
    else         { xq = ty * FOPI * atanf(xc / yd); yq = ty; }
    if (sq_xy < EPS) { xq = 0.f; yq = 0.f; }

    float c0 = (xq + 1.f) * 2.5f, c1 = (yq + 1.f) * 2.5f, c2 = (zc + 1.f) * 2.5f;
    float f0 = floorf(c0), f1 = floorf(c1), f2 = floorf(c2);
    int i0x = min(max((int)f0, 0), KSZ - 1);
    int i0y = min(max((int)f1, 0), KSZ - 1);
    int i0z = min(max((int)f2, 0), KSZ - 1);
    unsigned packed = (unsigned)i0x | ((unsigned)i0y << 8) | ((unsigned)i0z << 16) | (m << 24);
    g_pairs[idx] = make_float4(__uint_as_float(packed), c0 - f0, c1 - f1, c2 - f2);
}

__global__ void count_kernel(const void* __restrict__ nmask) {
    int j = blockIdx.x * blockDim.x + threadIdx.x;
    if (j >= NPTS) return;
    int s = 0;
#pragma unroll
    for (int k = 0; k < KNB; k++) s += (int)read_mask(nmask, j * KNB + k);
    g_cnt[j] = (float)s;
}

// ---------------- W transpose + hi/lo split (layers 2/3) ----------------
__global__ void wsplit_kernel(const float* __restrict__ W, int Kd, int Cout, int ldap) {
    int idx = blockIdx.x * 256 + threadIdx.x;
    if (idx >= Cout * ldap) return;
    int o = idx / ldap, k = idx - o * ldap;
    float v = (k < Kd) ? W[(size_t)k * Cout + o] : 0.f;
    __nv_bfloat16 h = __float2bfloat16(v);
    __nv_bfloat16 l = __float2bfloat16(v - __bfloat162float(h));
    g_Wth[(size_t)o * ldap + k] = h;
    g_Wtl[(size_t)o * ldap + k] = l;
}

// ---------------- scatter (+ fused g_acc zeroing): build A in shared, emit bf16 hi/lo ----------------
template <int CIN>
__global__ void scatter_kernel(const float* __restrict__ X, const int* __restrict__ nidx,
                               int src_sel, int lda) {
    extern __shared__ float sm[];
    float* A    = sm;                              // MCELLS*CIN
    float* feat = A + MCELLS * CIN;                // KNB*CIN
    float* wS   = feat + KNB * CIN;                // 256
    unsigned short* cellS = (unsigned short*)(wS + KNB * 8);

    const float* __restrict__ src = (src_sel == 1) ? g_X1 : ((src_sel == 2) ? g_X2 : X);
    int j = blockIdx.x;
    int tid = threadIdx.x;

    // fused: zero the fp32 accumulator (grid 10000x256 covers 640k)
    {
        int z = blockIdx.x * 256 + tid;
        if (z < NPTS * 64) g_acc[z] = 0.f;
    }

    for (int i = tid; i < MCELLS * CIN; i += 256) A[i] = 0.f;
    for (int i = tid; i < KNB * CIN; i += 256) {
        int k = i / CIN, c = i - k * CIN;
        feat[i] = src[(size_t)nidx[j * KNB + k] * CIN + c];
    }
    if (tid < KNB) {
        float4 p = g_pairs[j * KNB + tid];
        unsigned pk = __float_as_uint(p.x);
        int ix0 = pk & 255, iy0 = (pk >> 8) & 255, iz0 = (pk >> 16) & 255;
        float mk = (pk >> 24) ? 1.f : 0.f;
        int ix[2] = { ix0, min(ix0 + 1, KSZ - 1) };
        int iy[2] = { iy0, min(iy0 + 1, KSZ - 1) };
        int iz[2] = { iz0, min(iz0 + 1, KSZ - 1) };
        float wx[2] = { 1.f - p.y, p.y };
        float wy[2] = { 1.f - p.z, p.z };
        float wz[2] = { 1.f - p.w, p.w };
#pragma unroll
        for (int c8 = 0; c8 < 8; c8++) {
            int cx = c8 >> 2, cy = (c8 >> 1) & 1, cz = c8 & 1;
            cellS[tid * 8 + c8] = (unsigned short)((ix[cx] * KSZ + iy[cy]) * KSZ + iz[cz]);
            wS[tid * 8 + c8] = wx[cx] * wy[cy] * wz[cz] * mk;
        }
    }
    __syncthreads();

    for (int base = 0; base < KNB * 8 * CIN; base += 256) {
        int idx = base + tid;
        int p = idx / CIN, c = idx - p * CIN;
        float w = wS[p];
        if (w != 0.f) atomicAdd(&A[cellS[p] * CIN + c], w * feat[(p >> 3) * CIN + c]);
    }
    __syncthreads();

    // fp32 -> bf16 hi/lo, 8 values per 16B streaming store (avoid L2 pollution)
    uint4* dh = (uint4*)(g_Ah + (size_t)j * lda);
    uint4* dl = (uint4*)(g_Al + (size_t)j * lda);
    const int NV = MCELLS * CIN;
    for (int i = tid * 8; i < lda; i += 256 * 8) {
        uint32_t hw[4], lw[4];
#pragma unroll
        for (int p = 0; p < 4; p++) {
            int e = i + p * 2;
            float v0 = (e     < NV) ? A[e]     : 0.f;
            float v1 = (e + 1 < NV) ? A[e + 1] : 0.f;
            uint32_t hp = packbf2(v0, v1);
            float h0 = __uint_as_float(hp << 16);
            float h1 = __uint_as_float(hp & 0xFFFF0000u);
            hw[p] = hp;
            lw[p] = packbf2(v0 - h0, v1 - h1);
        }
        __stcs(&dh[i >> 3], make_uint4(hw[0], hw[1], hw[2], hw[3]));
        __stcs(&dl[i >> 3], make_uint4(lw[0], lw[1], lw[2], lw[3]));
    }
}

// ---------------- persistent balanced bf16 mma.sync GEMM (3-product fp32 emulation) ---------
// Fixed grid = 3*SMs CTAs; each walks a contiguous range of the flattened
// (mtile, kchunk) work list, register-accumulating and atomic-flushing at mtile
// boundaries. CTA: 256 thr / 8 warps; mtile = 128 rows; k chunk = 32.
// smem stage: Ah[128x40] Al[128x40] Bh[64x40] Bl[64x40] bf16 (stride 40 elem = 80 B)
#define STG 30720
#define OFF_AL 10240
#define OFF_BH 20480
#define OFF_BL 25600

template <int NC>
__launch_bounds__(256, 3)
__global__ void mma_kernel(int lda, int nch, int gridp) {
    extern __shared__ __align__(16) char smraw[];
    uint32_t sbase = smem_u32(smraw);
    int tid = threadIdx.x;
    int wid = tid >> 5, lane = tid & 31;

    // ldmatrix lane addressing
    int sel = lane >> 3, l8 = lane & 7;
    uint32_t aoff = (uint32_t)((wid * 16 + l8 + (sel & 1) * 8) * 80 + ((sel >> 1) * 8) * 2);
    uint32_t boff = (uint32_t)(((sel >> 1) * 8 + l8) * 80 + ((sel & 1) * 8) * 2);

    long total = (long)MT * nch;
    int g = blockIdx.x;
    int beg = (int)(total * g / gridp);
    int end = (int)(total * (g + 1) / gridp);
    if (beg >= end) return;

    float acc[NC / 8][4];
#pragma unroll
    for (int t = 0; t < NC / 8; t++)
#pragma unroll
        for (int q = 0; q < 4; q++) acc[t][q] = 0.f;

    auto load_stage = [&](int mt, int kc, int s) {
        uint32_t st = sbase + s * STG;
        int m0 = mt * 128;
        size_t k0 = (size_t)kc * 32;
        for (int idx = tid; idx < 512; idx += 256) {
            int r = idx >> 2, sg = idx & 3;
            size_t go = (size_t)(m0 + r) * lda + k0;
            cpa16(st + r * 80 + sg * 16,          (const char*)(g_Ah + go) + sg * 16);
            cpa16(st + OFF_AL + r * 80 + sg * 16, (const char*)(g_Al + go) + sg * 16);
        }
        for (int idx = tid; idx < NC * 4; idx += 256) {
            int o = idx >> 2, sg = idx & 3;
            size_t go = (size_t)o * lda + k0;
            cpa16(st + OFF_BH + o * 80 + sg * 16, (const char*)(g_Wth + go) + sg * 16);
            cpa16(st + OFF_BL + o * 80 + sg * 16, (const char*)(g_Wtl + go) + sg * 16);
        }
        asm volatile("cp.async.commit_group;" ::: "memory");
    };

    int cur_mt = beg / nch;
    load_stage(cur_mt, beg - cur_mt * nch, 0);

    for (int i = beg; i < end; i++) {
        int ni = i + 1;
        int nmt = -1;
        if (ni < end) {
            nmt = ni / nch;
            load_stage(nmt, ni - nmt * nch, (ni - beg) & 1);
            asm volatile("cp.async.wait_group 1;" ::: "memory");
        } else {
            asm volatile("cp.async.wait_group 0;" ::: "memory");
        }
        __syncthreads();

        uint32_t st = sbase + ((i - beg) & 1) * STG;
#pragma unroll
        for (int ks = 0; ks < 2; ks++) {
            uint32_t ah[4], al[4];
            ldmx4(ah, st + aoff + ks * 32);
            ldmx4(al, st + OFF_AL + aoff + ks * 32);
#pragma unroll
            for (int ng = 0; ng < NC / 16; ng++) {
                uint32_t bh[4], bl[4];
                uint32_t bb = boff + (uint32_t)(ng * 16 * 80) + ks * 32;
                ldmx4(bh, st + OFF_BH + bb);
                ldmx4(bl, st + OFF_BL + bb);
                mma16816(acc[2 * ng],     ah, bh[0], bh[1]);
                mma16816(acc[2 * ng],     ah, bl[0], bl[1]);
                mma16816(acc[2 * ng],     al, bh[0], bh[1]);
                mma16816(acc[2 * ng + 1], ah, bh[2], bh[3]);
                mma16816(acc[2 * ng + 1], ah, bl[2], bl[3]);
                mma16816(acc[2 * ng + 1], al, bh[2], bh[3]);
            }
        }
        __syncthreads();

        if (nmt != cur_mt) {
            // flush accumulators for cur_mt
            int m0 = cur_mt * 128;
            int gg = lane >> 2, tg = lane & 3;
            int r0 = m0 + wid * 16 + gg;
            int r1 = r0 + 8;
#pragma unroll
            for (int nt = 0; nt < NC / 8; nt++) {
                int col = nt * 8 + tg * 2;
                if (r0 < NPTS) {
                    atomicAdd(&g_acc[r0 * NC + col],     acc[nt][0]);
                    atomicAdd(&g_acc[r0 * NC + col + 1], acc[nt][1]);
                }
                if (r1 < NPTS) {
                    atomicAdd(&g_acc[r1 * NC + col],     acc[nt][2]);
                    atomicAdd(&g_acc[r1 * NC + col + 1], acc[nt][3]);
                }
#pragma unroll
                for (int q = 0; q < 4; q++) acc[nt][q] = 0.f;
            }
            cur_mt = nmt;
        }
    }
}

// ---------------- finalize: normalize by neighbor count, + bias, ReLU ----------------
__global__ void finalize_kernel(const float* __restrict__ bias, int Cout, int dst_sel) {
    int idx = blockIdx.x * 256 + threadIdx.x;
    if (idx >= NPTS * Cout) return;
    int j = idx / Cout, co = idx - j * Cout;
    float v = g_acc[idx];
    float c = g_cnt[j];
    if (c > 0.f) v /= c;
    v = fmaxf(v + bias[co], 0.f);
    if (dst_sel == 1) g_X1[idx] = v;
    else if (dst_sel == 2) g_X2[idx] = v;
    else g_X3[idx] = v;
}

// ---------------- fused FC chain: 32->64->64->32->3 ----------------
__global__ void fc_kernel(const float* __restrict__ Wf1, const float* __restrict__ bf1,
                          const float* __restrict__ Wf2, const float* __restrict__ bf2,
                          const float* __restrict__ Wf3, const float* __restrict__ bf3,
                          const float* __restrict__ Wo,  const float* __restrict__ bo,
                          float* __restrict__ out) {
    __shared__ float w1[32 * 64], w2[64 * 64], w3[64 * 32], wo[32 * 3];
    __shared__ float bb1[64], bb2[64], bb3[32], bbo[3];
    int tid = threadIdx.x;  // 128
    for (int i = tid; i < 2048; i += 128) w1[i] = Wf1[i];
    for (int i = tid; i < 4096; i += 128) w2[i] = Wf2[i];
    for (int i = tid; i < 2048; i += 128) w3[i] = Wf3[i];
    for (int i = tid; i < 96; i += 128) wo[i] = Wo[i];
    if (tid < 64) { bb1[tid] = bf1[tid]; bb2[tid] = bf2[tid]; }
    if (tid < 32) bb3[tid] = bf3[tid];
    if (tid < 3)  bbo[tid] = bo[tid];
    __syncthreads();

    int j = blockIdx.x * 128 + tid;
    if (j >= NPTS) return;

    float x[32];
#pragma unroll
    for (int i = 0; i < 32; i++) x[i] = g_X3[j * 32 + i];
    float y[64];
    for (int o = 0; o < 64; o++) {
        float s = bb1[o];
#pragma unroll
        for (int i = 0; i < 32; i++) s += x[i] * w1[i * 64 + o];
        y[o] = fmaxf(s, 0.f);
    }
    float z[64];
    for (int o = 0; o < 64; o++) {
        float s = bb2[o];
#pragma unroll
        for (int i = 0; i < 64; i++) s += y[i] * w2[i * 64 + o];
        z[o] = fmaxf(s, 0.f);
    }
    float t[32];
    for (int o = 0; o < 32; o++) {
        float s = bb3[o];
#pragma unroll
        for (int i = 0; i < 64; i++) s += z[i] * w3[i * 32 + o];
        t[o] = fmaxf(s, 0.f);
    }
    for (int o = 0; o < 3; o++) {
        float s = bbo[o];
#pragma unroll
        for (int i = 0; i < 32; i++) s += t[i] * wo[i * 3 + o];
        out[j * 3 + o] = s;
    }
}

// ---------------- launch ----------------
extern "C" void kernel_launch(void* const* d_in, const int* in_sizes, int n_in,
                              void* d_out, int out_size) {
    const float* feats = (const float*)d_in[0];
    const float* pos   = (const float*)d_in[1];
    const int*   nidx  = (const int*)d_in[2];
    const void*  nmask = d_in[3];
    const float* W1 = (const float*)d_in[4];  const float* b1 = (const float*)d_in[5];
    const float* W2 = (const float*)d_in[6];  const float* b2 = (const float*)d_in[7];
    const float* W3 = (const float*)d_in[8];  const float* b3 = (const float*)d_in[9];
    const float* Wf1 = (const float*)d_in[10]; const float* bf1 = (const float*)d_in[11];
    const float* Wf2 = (const float*)d_in[12]; const float* bf2 = (const float*)d_in[13];
    const float* Wf3 = (const float*)d_in[14]; const float* bf3 = (const float*)d_in[15];
    const float* Wo  = (const float*)d_in[16]; const float* bo  = (const float*)d_in[17];
    float* out = (float*)d_out;

    const int SMEM64 = (MCELLS * 64 + KNB * 64 + 256) * 4 + 512;
    const int SMEM4  = (MCELLS * 4  + KNB * 4  + 256) * 4 + 512;
    const int SMEM_MMA = 2 * STG;   // 60 KB -> 3 CTAs/SM with reg cap
    cudaFuncSetAttribute(scatter_kernel<64>, cudaFuncAttributeMaxDynamicSharedMemorySize, SMEM64);
    cudaFuncSetAttribute(scatter_kernel<4>,  cudaFuncAttributeMaxDynamicSharedMemorySize, SMEM4);
    cudaFuncSetAttribute(mma_kernel<64>, cudaFuncAttributeMaxDynamicSharedMemorySize, SMEM_MMA);
    cudaFuncSetAttribute(mma_kernel<32>, cudaFuncAttributeMaxDynamicSharedMemorySize, SMEM_MMA);

    // persistent grid = occupancy * SM count (host-side queries; graph-safe)
    int nsm = 148;
    cudaDeviceGetAttribute(&nsm, cudaDevAttrMultiProcessorCount, 0);
    int nb64 = 1, nb32 = 1;
    cudaOccupancyMaxActiveBlocksPerMultiprocessor(&nb64, mma_kernel<64>, 256, SMEM_MMA);
    cudaOccupancyMaxActiveBlocksPerMultiprocessor(&nb32, mma_kernel<32>, 256, SMEM_MMA);
    if (nb64 < 1) nb64 = 1;
    if (nb32 < 1) nb32 = 1;
    int grid64 = nb64 * nsm, grid32 = nb32 * nsm;

    // ---- layer 1 (ordered so ncu capture window = my index 3 = mma_kernel<64>) ----
    detect_mask_kernel<<<(NPTS * KNB + 255) / 256, 256>>>((const unsigned char*)nmask);   // 0
    geom_kernel<<<(NPTS * KNB + 255) / 256, 256>>>(pos, nidx, nmask, W1);                 // 1 (+wsplit W1)
    scatter_kernel<4><<<NPTS, 256, SMEM4>>>(feats, nidx, 0, LDA1);                        // 2 (+zero acc)
    mma_kernel<64><<<grid64, 256, SMEM_MMA>>>(LDA1, LDA1 / 32, grid64);                   // 3 <- profiled
    count_kernel<<<(NPTS + 255) / 256, 256>>>(nmask);
    finalize_kernel<<<(NPTS * 64 + 255) / 256, 256>>>(b1, 64, 1);

    // ---- layer 2: 64 -> 64, lda = 13824 (432 chunks) ----
    wsplit_kernel<<<(64 * KD2 + 255) / 256, 256>>>(W2, KD2, 64, KD2);
    scatter_kernel<64><<<NPTS, 256, SMEM64>>>(nullptr, nidx, 1, KD2);
    mma_kernel<64><<<grid64, 256, SMEM_MMA>>>(KD2, KD2 / 32, grid64);
    finalize_kernel<<<(NPTS * 64 + 255) / 256, 256>>>(b2, 64, 2);

    // ---- layer 3: 64 -> 32 ----
    wsplit_kernel<<<(32 * KD2 + 255) / 256, 256>>>(W3, KD2, 32, KD2);
    scatter_kernel<64><<<NPTS, 256, SMEM64>>>(nullptr, nidx, 2, KD2);
    mma_kernel<32><<<grid32, 256, SMEM_MMA>>>(KD2, KD2 / 32, grid32);
    finalize_kernel<<<(NPTS * 32 + 255) / 256, 256>>>(b3, 32, 3);

    // FC head
    fc_kernel<<<(NPTS + 127) / 128, 128>>>(Wf1, bf1, Wf2, bf2, Wf3, bf3, Wo, bo, out);
}

// round 12
// speedup vs baseline: 1.1917x; 1.1917x over previous
#include <cuda_runtime.h>
#include <cuda_bf16.h>
#include <cuda_fp16.h>
#include <cstdint>

#define NPTS 10000
#define KNB 32
#define KSZ 6
#define MCELLS 216           // 6*6*6
#define KD2 (MCELLS * 64)    // 13824
#define LDA1 896             // layer1 Kd=864 padded to 28*32
#define RPAD 10112           // 79 tiles * 128 rows
#define MT 79                // M tiles

// ---------------- device scratch (static: no allocs allowed) ----------------
__device__ float4 g_pairs[NPTS * KNB];
__device__ float  g_cnt[NPTS];
__device__ __half g_Af[(size_t)RPAD * KD2];           // scatter output fp16 (277 MB)
__device__ __half g_Wtf[64 * KD2];                    // transposed W fp16 [Cout][lda]
__device__ float  g_acc[NPTS * 64];                   // fp32 accumulator
__device__ float  g_X1[NPTS * 64];
__device__ float  g_X2[NPTS * 64];
__device__ float  g_X3[NPTS * 32];
__device__ int    g_mask_is_u8;

__device__ __forceinline__ float sgnf(float v) { return (v > 0.f) ? 1.f : ((v < 0.f) ? -1.f : 0.f); }

// ---------------- PTX helpers (all sm_80+ baseline; no 103a features) ----------------
__device__ __forceinline__ uint32_t smem_u32(const void* p) {
    uint32_t a;
    asm("{ .reg .u64 t; cvta.to.shared.u64 t, %1; cvt.u32.u64 %0, t; }" : "=r"(a) : "l"(p));
    return a;
}
__device__ __forceinline__ void cpa16(uint32_t dst, const void* src) {
    asm volatile("cp.async.cg.shared.global [%0], [%1], 16;" :: "r"(dst), "l"(src) : "memory");
}
__device__ __forceinline__ void ldmx4(uint32_t* r, uint32_t addr) {
    asm volatile("ldmatrix.sync.aligned.m8n8.x4.shared.b16 {%0,%1,%2,%3}, [%4];"
                 : "=r"(r[0]), "=r"(r[1]), "=r"(r[2]), "=r"(r[3]) : "r"(addr));
}
__device__ __forceinline__ void mma16816h(float* d, const uint32_t* a, uint32_t b0, uint32_t b1) {
    asm volatile(
        "mma.sync.aligned.m16n8k16.row.col.f32.f16.f16.f32 "
        "{%0,%1,%2,%3}, {%4,%5,%6,%7}, {%8,%9}, {%0,%1,%2,%3};"
        : "+f"(d[0]), "+f"(d[1]), "+f"(d[2]), "+f"(d[3])
        : "r"(a[0]), "r"(a[1]), "r"(a[2]), "r"(a[3]), "r"(b0), "r"(b1));
}

// ---------------- mask dtype detection ----------------
__global__ void detect_mask_kernel(const unsigned char* __restrict__ bytes) {
    int i = blockIdx.x * 256 + threadIdx.x;
    if (i >= NPTS * KNB) return;
    if ((i & 3) != 0 && bytes[i] != 0) atomicOr(&g_mask_is_u8, 1);
}
__device__ __forceinline__ unsigned read_mask(const void* m, int idx) {
    if (g_mask_is_u8) return ((const unsigned char*)m)[idx] ? 1u : 0u;
    return ((const int*)m)[idx] ? 1u : 0u;
}

// ---------------- geometry (+ fused wsplit of W1) ----------------
__global__ void geom_kernel(const float* __restrict__ pos, const int* __restrict__ nidx,
                            const void* __restrict__ nmask, const float* __restrict__ W1) {
    int idx = blockIdx.x * blockDim.x + threadIdx.x;

    // fused: transpose W1 into g_Wtf (64 x LDA1, fp16)
    if (idx < 64 * LDA1) {
        int o = idx / LDA1, k = idx - o * LDA1;
        float v = (k < MCELLS * 4) ? W1[(size_t)k * 64 + o] : 0.f;
        g_Wtf[(size_t)o * LDA1 + k] = __float2half_rn(v);
    }

    if (idx >= NPTS * KNB) return;
    int j = idx >> 5;
    int n = nidx[idx];
    unsigned m = read_mask(nmask, idx);

    const float EPS = 1e-12f;
    float x = (pos[n * 3 + 0] - pos[j * 3 + 0]) * (2.0f / 3.0f);
    float y = (pos[n * 3 + 1] - pos[j * 3 + 1]) * (2.0f / 3.0f);
    float z = (pos[n * 3 + 2] - pos[j * 3 + 2]) * (2.0f / 3.0f);

    float sq = x * x + y * y + z * z;
    float norm = sqrtf(fmaxf(sq, EPS));
    float rho2 = x * x + y * y;
    bool in_cone = (1.25f * z * z > rho2);
    float s, zc;
    if (in_cone) { s = sqrtf(3.0f * norm / (norm + fabsf(z))); zc = sgnf(z) * norm; }
    else         { s = norm / sqrtf(fmaxf(rho2, EPS));         zc = 1.5f * z; }
    float xc = x * s, yc = y * s;
    if (sq < EPS) { xc = 0.f; yc = 0.f; zc = 0.f; }

    float sq_xy = xc * xc + yc * yc;
    float norm_xy = sqrtf(fmaxf(sq_xy, EPS));
    bool x_major = fabsf(yc) <= fabsf(xc);
    float xd = (fabsf(xc) < EPS) ? 1.f : xc;
    float yd = (fabsf(yc) < EPS) ? 1.f : yc;
    float tx = sgnf(xc) * norm_xy, ty = sgnf(yc) * norm_xy;
    const float FOPI = 1.2732395447351628f;
    float xq, yq;
    if (x_major) { xq = tx;                        yq = tx * FOPI * atanf(yc / xd); }
    else         { xq = ty * FOPI * atanf(xc / yd); yq = ty; }
    if (sq_xy < EPS) { xq = 0.f; yq = 0.f; }

    float c0 = (xq + 1.f) * 2.5f, c1 = (yq + 1.f) * 2.5f, c2 = (zc + 1.f) * 2.5f;
    float f0 = floorf(c0), f1 = floorf(c1), f2 = floorf(c2);
    int i0x = min(max((int)f0, 0), KSZ - 1);
    int i0y = min(max((int)f1, 0), KSZ - 1);
    int i0z = min(max((int)f2, 0), KSZ - 1);
    unsigned packed = (unsigned)i0x | ((unsigned)i0y << 8) | ((unsigned)i0z << 16) | (m << 24);
    g_pairs[idx] = make_float4(__uint_as_float(packed), c0 - f0, c1 - f1, c2 - f2);
}

__global__ void count_kernel(const void* __restrict__ nmask) {
    int j = blockIdx.x * blockDim.x + threadIdx.x;
    if (j >= NPTS) return;
    int s = 0;
#pragma unroll
    for (int k = 0; k < KNB; k++) s += (int)read_mask(nmask, j * KNB + k);
    g_cnt[j] = (float)s;
}

// ---------------- W transpose (layers 2/3), fp16 ----------------
__global__ void wsplit_kernel(const float* __restrict__ W, int Kd, int Cout, int ldap) {
    int idx = blockIdx.x * 256 + threadIdx.x;
    if (idx >= Cout * ldap) return;
    int o = idx / ldap, k = idx - o * ldap;
    float v = (k < Kd) ? W[(size_t)k * Cout + o] : 0.f;
    g_Wtf[(size_t)o * ldap + k] = __float2half_rn(v);
}

// ---------------- scatter (+ fused g_acc zeroing): build A in shared, emit fp16 ----------------
template <int CIN>
__global__ void scatter_kernel(const float* __restrict__ X, const int* __restrict__ nidx,
                               int src_sel, int lda) {
    extern __shared__ float sm[];
    float* A    = sm;                              // MCELLS*CIN
    float* feat = A + MCELLS * CIN;                // KNB*CIN
    float* wS   = feat + KNB * CIN;                // 256
    unsigned short* cellS = (unsigned short*)(wS + KNB * 8);

    const float* __restrict__ src = (src_sel == 1) ? g_X1 : ((src_sel == 2) ? g_X2 : X);
    int j = blockIdx.x;
    int tid = threadIdx.x;

    // fused: zero the fp32 accumulator (grid 10000x256 covers 640k)
    {
        int z = blockIdx.x * 256 + tid;
        if (z < NPTS * 64) g_acc[z] = 0.f;
    }

    for (int i = tid; i < MCELLS * CIN; i += 256) A[i] = 0.f;
    for (int i = tid; i < KNB * CIN; i += 256) {
        int k = i / CIN, c = i - k * CIN;
        feat[i] = src[(size_t)nidx[j * KNB + k] * CIN + c];
    }
    if (tid < KNB) {
        float4 p = g_pairs[j * KNB + tid];
        unsigned pk = __float_as_uint(p.x);
        int ix0 = pk & 255, iy0 = (pk >> 8) & 255, iz0 = (pk >> 16) & 255;
        float mk = (pk >> 24) ? 1.f : 0.f;
        int ix[2] = { ix0, min(ix0 + 1, KSZ - 1) };
        int iy[2] = { iy0, min(iy0 + 1, KSZ - 1) };
        int iz[2] = { iz0, min(iz0 + 1, KSZ - 1) };
        float wx[2] = { 1.f - p.y, p.y };
        float wy[2] = { 1.f - p.z, p.z };
        float wz[2] = { 1.f - p.w, p.w };
#pragma unroll
        for (int c8 = 0; c8 < 8; c8++) {
            int cx = c8 >> 2, cy = (c8 >> 1) & 1, cz = c8 & 1;
            cellS[tid * 8 + c8] = (unsigned short)((ix[cx] * KSZ + iy[cy]) * KSZ + iz[cz]);
            wS[tid * 8 + c8] = wx[cx] * wy[cy] * wz[cz] * mk;
        }
    }
    __syncthreads();

    for (int base = 0; base < KNB * 8 * CIN; base += 256) {
        int idx = base + tid;
        int p = idx / CIN, c = idx - p * CIN;
        float w = wS[p];
        if (w != 0.f) atomicAdd(&A[cellS[p] * CIN + c], w * feat[(p >> 3) * CIN + c]);
    }
    __syncthreads();

    // fp32 -> fp16, 8 values per 16B streaming store
    uint4* df = (uint4*)(g_Af + (size_t)j * lda);
    const int NV = MCELLS * CIN;
    for (int i = tid * 8; i < lda; i += 256 * 8) {
        uint32_t w[4];
#pragma unroll
        for (int p = 0; p < 4; p++) {
            int e = i + p * 2;
            float v0 = (e     < NV) ? A[e]     : 0.f;
            float v1 = (e + 1 < NV) ? A[e + 1] : 0.f;
            __half2 h2 = __floats2half2_rn(v0, v1);
            w[p] = *(uint32_t*)&h2;
        }
        __stcs(&df[i >> 3], make_uint4(w[0], w[1], w[2], w[3]));
    }
}

// ---------------- persistent balanced fp16 mma.sync GEMM (single product) ----------------
// Fixed grid; each CTA walks a contiguous range of the flattened (mtile, kchunk)
// work list, register-accumulating, atomic-flushing at mtile boundaries.
// CTA: 256 thr / 8 warps; mtile = 128 rows; k chunk = 32.
// 4-stage cp.async ring; stage: A[128x40] + B[64x40] fp16 (stride 40 elem = 80 B)
#define NSTG 4
#define STG 15360
#define OFF_B 10240

template <int NC>
__launch_bounds__(256, 3)
__global__ void mma_kernel(int lda, int nch, int gridp) {
    extern __shared__ __align__(16) char smraw[];
    uint32_t sbase = smem_u32(smraw);
    int tid = threadIdx.x;
    int wid = tid >> 5, lane = tid & 31;

    // ldmatrix lane addressing
    int sel = lane >> 3, l8 = lane & 7;
    uint32_t aoff = (uint32_t)((wid * 16 + l8 + (sel & 1) * 8) * 80 + ((sel >> 1) * 8) * 2);
    uint32_t boff = (uint32_t)(((sel >> 1) * 8 + l8) * 80 + ((sel & 1) * 8) * 2);

    long total = (long)MT * nch;
    int g = blockIdx.x;
    int beg = (int)(total * g / gridp);
    int end = (int)(total * (g + 1) / gridp);
    int cnt = end - beg;
    if (cnt <= 0) return;

    float acc[NC / 8][4];
#pragma unroll
    for (int t = 0; t < NC / 8; t++)
#pragma unroll
        for (int q = 0; q < 4; q++) acc[t][q] = 0.f;

    auto load_stage = [&](int widx, int s) {
        uint32_t st = sbase + s * STG;
        int mt = widx / nch, kc = widx - mt * nch;
        int m0 = mt * 128;
        size_t k0 = (size_t)kc * 32;
        for (int idx = tid; idx < 512; idx += 256) {
            int r = idx >> 2, sg = idx & 3;
            cpa16(st + r * 80 + sg * 16,
                  (const char*)(g_Af + (size_t)(m0 + r) * lda + k0) + sg * 16);
        }
        for (int idx = tid; idx < NC * 4; idx += 256) {
            int o = idx >> 2, sg = idx & 3;
            cpa16(st + OFF_B + o * 80 + sg * 16,
                  (const char*)(g_Wtf + (size_t)o * lda + k0) + sg * 16);
        }
        asm volatile("cp.async.commit_group;" ::: "memory");
    };

    auto compute = [&](int s) {
        uint32_t st = sbase + s * STG;
#pragma unroll
        for (int ks = 0; ks < 2; ks++) {
            uint32_t a[4];
            ldmx4(a, st + aoff + ks * 32);
#pragma unroll
            for (int ng = 0; ng < NC / 16; ng++) {
                uint32_t b[4];
                ldmx4(b, st + OFF_B + boff + (uint32_t)(ng * 16 * 80) + ks * 32);
                mma16816h(acc[2 * ng],     a, b[0], b[1]);
                mma16816h(acc[2 * ng + 1], a, b[2], b[3]);
            }
        }
    };

    auto flush = [&](int mt) {
        int m0 = mt * 128;
        int gg = lane >> 2, tg = lane & 3;
        int r0 = m0 + wid * 16 + gg;
        int r1 = r0 + 8;
#pragma unroll
        for (int nt = 0; nt < NC / 8; nt++) {
            int col = nt * 8 + tg * 2;
            if (r0 < NPTS) {
                atomicAdd(&g_acc[r0 * NC + col],     acc[nt][0]);
                atomicAdd(&g_acc[r0 * NC + col + 1], acc[nt][1]);
            }
            if (r1 < NPTS) {
                atomicAdd(&g_acc[r1 * NC + col],     acc[nt][2]);
                atomicAdd(&g_acc[r1 * NC + col + 1], acc[nt][3]);
            }
#pragma unroll
            for (int q = 0; q < 4; q++) acc[nt][q] = 0.f;
        }
    };

    int cur_mt = beg / nch;

    if (cnt < NSTG) {
        // tiny range: load everything, then compute
        for (int p = 0; p < cnt; p++) load_stage(beg + p, p);
        asm volatile("cp.async.wait_group 0;" ::: "memory");
        __syncthreads();
        for (int i = 0; i < cnt; i++) {
            int mt = (beg + i) / nch;
            if (mt != cur_mt) { flush(cur_mt); cur_mt = mt; }
            compute(i);
        }
        flush(cur_mt);
        return;
    }

    for (int p = 0; p < NSTG - 1; p++) load_stage(beg + p, p);
    for (int i = 0; i < cnt; i++) {
        if (i + NSTG - 1 < cnt) load_stage(beg + i + NSTG - 1, (i + NSTG - 1) % NSTG);
        else asm volatile("cp.async.commit_group;" ::: "memory");
        asm volatile("cp.async.wait_group %0;" :: "n"(NSTG - 2) : "memory");
        __syncthreads();
        int mt = (beg + i) / nch;
        if (mt != cur_mt) { flush(cur_mt); cur_mt = mt; }
        compute(i % NSTG);
        __syncthreads();
    }
    flush(cur_mt);
}

// ---------------- finalize: normalize by neighbor count, + bias, ReLU ----------------
__global__ void finalize_kernel(const float* __restrict__ bias, int Cout, int dst_sel) {
    int idx = blockIdx.x * 256 + threadIdx.x;
    if (idx >= NPTS * Cout) return;
    int j = idx / Cout, co = idx - j * Cout;
    float v = g_acc[idx];
    float c = g_cnt[j];
    if (c > 0.f) v /= c;
    v = fmaxf(v + bias[co], 0.f);
    if (dst_sel == 1) g_X1[idx] = v;
    else if (dst_sel == 2) g_X2[idx] = v;
    else g_X3[idx] = v;
}

// ---------------- fused FC chain: 32->64->64->32->3 ----------------
__global__ void fc_kernel(const float* __restrict__ Wf1, const float* __restrict__ bf1,
                          const float* __restrict__ Wf2, const float* __restrict__ bf2,
                          const float* __restrict__ Wf3, const float* __restrict__ bf3,
                          const float* __restrict__ Wo,  const float* __restrict__ bo,
                          float* __restrict__ out) {
    __shared__ float w1[32 * 64], w2[64 * 64], w3[64 * 32], wo[32 * 3];
    __shared__ float bb1[64], bb2[64], bb3[32], bbo[3];
    int tid = threadIdx.x;  // 128
    for (int i = tid; i < 2048; i += 128) w1[i] = Wf1[i];
    for (int i = tid; i < 4096; i += 128) w2[i] = Wf2[i];
    for (int i = tid; i < 2048; i += 128) w3[i] = Wf3[i];
    for (int i = tid; i < 96; i += 128) wo[i] = Wo[i];
    if (tid < 64) { bb1[tid] = bf1[tid]; bb2[tid] = bf2[tid]; }
    if (tid < 32) bb3[tid] = bf3[tid];
    if (tid < 3)  bbo[tid] = bo[tid];
    __syncthreads();

    int j = blockIdx.x * 128 + tid;
    if (j >= NPTS) return;

    float x[32];
#pragma unroll
    for (int i = 0; i < 32; i++) x[i] = g_X3[j * 32 + i];
    float y[64];
    for (int o = 0; o < 64; o++) {
        float s = bb1[o];
#pragma unroll
        for (int i = 0; i < 32; i++) s += x[i] * w1[i * 64 + o];
        y[o] = fmaxf(s, 0.f);
    }
    float z[64];
    for (int o = 0; o < 64; o++) {
        float s = bb2[o];
#pragma unroll
        for (int i = 0; i < 64; i++) s += y[i] * w2[i * 64 + o];
        z[o] = fmaxf(s, 0.f);
    }
    float t[32];
    for (int o = 0; o < 32; o++) {
        float s = bb3[o];
#pragma unroll
        for (int i = 0; i < 64; i++) s += z[i] * w3[i * 32 + o];
        t[o] = fmaxf(s, 0.f);
    }
    for (int o = 0; o < 3; o++) {
        float s = bbo[o];
#pragma unroll
        for (int i = 0; i < 32; i++) s += t[i] * wo[i * 3 + o];
        out[j * 3 + o] = s;
    }
}

// ---------------- launch ----------------
extern "C" void kernel_launch(void* const* d_in, const int* in_sizes, int n_in,
                              void* d_out, int out_size) {
    const float* feats = (const float*)d_in[0];
    const float* pos   = (const float*)d_in[1];
    const int*   nidx  = (const int*)d_in[2];
    const void*  nmask = d_in[3];
    const float* W1 = (const float*)d_in[4];  const float* b1 = (const float*)d_in[5];
    const float* W2 = (const float*)d_in[6];  const float* b2 = (const float*)d_in[7];
    const float* W3 = (const float*)d_in[8];  const float* b3 = (const float*)d_in[9];
    const float* Wf1 = (const float*)d_in[10]; const float* bf1 = (const float*)d_in[11];
    const float* Wf2 = (const float*)d_in[12]; const float* bf2 = (const float*)d_in[13];
    const float* Wf3 = (const float*)d_in[14]; const float* bf3 = (const float*)d_in[15];
    const float* Wo  = (const float*)d_in[16]; const float* bo  = (const float*)d_in[17];
    float* out = (float*)d_out;

    const int SMEM64 = (MCELLS * 64 + KNB * 64 + 256) * 4 + 512;
    const int SMEM4  = (MCELLS * 4  + KNB * 4  + 256) * 4 + 512;
    const int SMEM_MMA = NSTG * STG;   // 61440 B -> 3 CTAs/SM
    cudaFuncSetAttribute(scatter_kernel<64>, cudaFuncAttributeMaxDynamicSharedMemorySize, SMEM64);
    cudaFuncSetAttribute(scatter_kernel<4>,  cudaFuncAttributeMaxDynamicSharedMemorySize, SMEM4);
    cudaFuncSetAttribute(mma_kernel<64>, cudaFuncAttributeMaxDynamicSharedMemorySize, SMEM_MMA);
    cudaFuncSetAttribute(mma_kernel<32>, cudaFuncAttributeMaxDynamicSharedMemorySize, SMEM_MMA);

    // persistent grid = occupancy * SM count (host-side queries; graph-safe)
    int nsm = 148;
    cudaDeviceGetAttribute(&nsm, cudaDevAttrMultiProcessorCount, 0);
    int nb64 = 1, nb32 = 1;
    cudaOccupancyMaxActiveBlocksPerMultiprocessor(&nb64, mma_kernel<64>, 256, SMEM_MMA);
    cudaOccupancyMaxActiveBlocksPerMultiprocessor(&nb32, mma_kernel<32>, 256, SMEM_MMA);
    if (nb64 < 1) nb64 = 1;
    if (nb32 < 1) nb32 = 1;
    int grid64 = nb64 * nsm, grid32 = nb32 * nsm;

    // ---- layer 1 (ordered so ncu capture window = my index 3 = mma_kernel<64>) ----
    detect_mask_kernel<<<(NPTS * KNB + 255) / 256, 256>>>((const unsigned char*)nmask);   // 0
    geom_kernel<<<(NPTS * KNB + 255) / 256, 256>>>(pos, nidx, nmask, W1);                 // 1 (+wsplit W1)
    scatter_kernel<4><<<NPTS, 256, SMEM4>>>(feats, nidx, 0, LDA1);                        // 2 (+zero acc)
    mma_kernel<64><<<grid64, 256, SMEM_MMA>>>(LDA1, LDA1 / 32, grid64);                   // 3 <- profiled
    count_kernel<<<(NPTS + 255) / 256, 256>>>(nmask);
    finalize_kernel<<<(NPTS * 64 + 255) / 256, 256>>>(b1, 64, 1);

    // ---- layer 2: 64 -> 64, lda = 13824 (432 chunks) ----
    wsplit_kernel<<<(64 * KD2 + 255) / 256, 256>>>(W2, KD2, 64, KD2);
    scatter_kernel<64><<<NPTS, 256, SMEM64>>>(nullptr, nidx, 1, KD2);
    mma_kernel<64><<<grid64, 256, SMEM_MMA>>>(KD2, KD2 / 32, grid64);
    finalize_kernel<<<(NPTS * 64 + 255) / 256, 256>>>(b2, 64, 2);

    // ---- layer 3: 64 -> 32 ----
    wsplit_kernel<<<(32 * KD2 + 255) / 256, 256>>>(W3, KD2, 32, KD2);
    scatter_kernel<64><<<NPTS, 256, SMEM64>>>(nullptr, nidx, 2, KD2);
    mma_kernel<32><<<grid32, 256, SMEM_MMA>>>(KD2, KD2 / 32, grid32);
    finalize_kernel<<<(NPTS * 32 + 255) / 256, 256>>>(b3, 32, 3);

    // FC head
    fc_kernel<<<(NPTS + 127) / 128, 128>>>(Wf1, bf1, Wf2, bf2, Wf3, bf3, Wo, bo, out);
}